// round 3
// baseline (speedup 1.0000x reference)
#include <cuda_runtime.h>
#include <cstdint>

namespace {

constexpr int Bb = 2, Hh = 16, Tt = 4096, Dd = 64;
constexpr int BM = 128;           // q rows per CTA
constexpr int BN = 64;            // kv rows per tile
constexpr int QS = 68;            // Q smem row stride (floats) -> conflict-free A-frag loads
constexpr int KSs = 68;           // K smem row stride -> conflict-free QK B-frag loads
constexpr int VSs = 72;           // V smem row stride -> conflict-free PV B-frag loads
constexpr int SMEM_U32 = BM * QS + BN * KSs + BN * VSs;
constexpr int SMEM_BYTES = SMEM_U32 * 4;
constexpr float QSCALE = 0.125f * 1.44269504088896340736f;  // 1/sqrt(64) * log2(e)

__device__ __forceinline__ uint32_t f2tf(float f) {
    uint32_t u;
    asm("cvt.rna.tf32.f32 %0, %1;" : "=r"(u) : "f"(f));
    return u;
}

__device__ __forceinline__ float ex2f(float x) {
    float y;
    asm("ex2.approx.f32 %0, %1;" : "=f"(y) : "f"(x));
    return y;
}

__device__ __forceinline__ void mma_tf32(float d[4], const uint32_t a[4],
                                         uint32_t b0, uint32_t b1) {
    asm("mma.sync.aligned.m16n8k8.row.col.f32.tf32.tf32.f32 "
        "{%0,%1,%2,%3}, {%4,%5,%6,%7}, {%8,%9}, {%0,%1,%2,%3};"
        : "+f"(d[0]), "+f"(d[1]), "+f"(d[2]), "+f"(d[3])
        : "r"(a[0]), "r"(a[1]), "r"(a[2]), "r"(a[3]), "r"(b0), "r"(b1));
}

__global__ void __launch_bounds__(256, 1)
fa_fwd(const float* __restrict__ Q, const float* __restrict__ K,
       const float* __restrict__ V, float* __restrict__ O) {
    extern __shared__ uint32_t sm_[];
    uint32_t* qs  = sm_;
    uint32_t* ksm = sm_ + BM * QS;
    uint32_t* vsm = sm_ + BM * QS + BN * KSs;

    const int tid  = threadIdx.x;
    const int warp = tid >> 5;
    const int lane = tid & 31;
    const int g = lane >> 2;   // group id (row within 8)
    const int t = lane & 3;    // thread in group

    const int bh    = blockIdx.y;
    const int qb    = (int)gridDim.x - 1 - (int)blockIdx.x;  // longest-first
    const int qbase = qb * BM;
    const size_t base = (size_t)bh * Tt * Dd;
    const float* Qp = Q + base;
    const float* Kp = K + base;
    const float* Vp = V + base;
    float*       Op = O + base;

    // ---- Q tile -> smem (pre-scaled, tf32) ----
    {
        int r  = tid >> 1;          // 0..127
        int c0 = (tid & 1) * 32;
        const float4* src = reinterpret_cast<const float4*>(
            Qp + (size_t)(qbase + r) * Dd + c0);
        uint32_t* dst = qs + r * QS + c0;
#pragma unroll
        for (int i = 0; i < 8; i++) {
            float4 a = src[i];
            dst[i * 4 + 0] = f2tf(a.x * QSCALE);
            dst[i * 4 + 1] = f2tf(a.y * QSCALE);
            dst[i * 4 + 2] = f2tf(a.z * QSCALE);
            dst[i * 4 + 3] = f2tf(a.w * QSCALE);
        }
    }
    __syncthreads();

    // ---- Q fragments in registers (held for whole kernel) ----
    uint32_t qf[8][4];
    const int mrow = warp * 16;
#pragma unroll
    for (int kk = 0; kk < 8; kk++) {
        int col = kk * 8 + t;
        qf[kk][0] = qs[(mrow + g)     * QS + col];
        qf[kk][1] = qs[(mrow + g + 8) * QS + col];
        qf[kk][2] = qs[(mrow + g)     * QS + col + 4];
        qf[kk][3] = qs[(mrow + g + 8) * QS + col + 4];
    }

    float o[8][4];
#pragma unroll
    for (int nd = 0; nd < 8; nd++) {
        o[nd][0] = 0.f; o[nd][1] = 0.f; o[nd][2] = 0.f; o[nd][3] = 0.f;
    }
    const float NEGINF = __int_as_float(0xff800000u);
    float m_lo = NEGINF, m_hi = NEGINF, l_lo = 0.f, l_hi = 0.f;

    const int jmax = 2 * qb + 1;   // causal: kv tiles with kvbase <= q_max
    for (int j = 0; j <= jmax; j++) {
        const int kvbase = j * BN;

        __syncthreads();   // previous iteration's smem reads done
        {
            int r  = tid >> 2;         // 0..63
            int c0 = (tid & 3) * 16;
            const float4* sk = reinterpret_cast<const float4*>(
                Kp + (size_t)(kvbase + r) * Dd + c0);
            const float4* sv = reinterpret_cast<const float4*>(
                Vp + (size_t)(kvbase + r) * Dd + c0);
            uint32_t* dk = ksm + r * KSs + c0;
            uint32_t* dv = vsm + r * VSs + c0;
#pragma unroll
            for (int i = 0; i < 4; i++) {
                float4 a = sk[i];
                dk[i * 4 + 0] = f2tf(a.x); dk[i * 4 + 1] = f2tf(a.y);
                dk[i * 4 + 2] = f2tf(a.z); dk[i * 4 + 3] = f2tf(a.w);
            }
#pragma unroll
            for (int i = 0; i < 4; i++) {
                float4 a = sv[i];
                dv[i * 4 + 0] = f2tf(a.x); dv[i * 4 + 1] = f2tf(a.y);
                dv[i * 4 + 2] = f2tf(a.z); dv[i * 4 + 3] = f2tf(a.w);
            }
        }
        __syncthreads();

        // fully-masked warp tile (above diagonal) -> skip compute entirely
        const bool active = (kvbase <= qbase + mrow + 15);
        if (active) {
            // ---- S = Q K^T (log2 domain) ----
            float s[8][4];
#pragma unroll
            for (int n = 0; n < 8; n++) {
                s[n][0] = 0.f; s[n][1] = 0.f; s[n][2] = 0.f; s[n][3] = 0.f;
            }
#pragma unroll
            for (int kk = 0; kk < 8; kk++) {
#pragma unroll
                for (int n = 0; n < 8; n++) {
                    uint32_t b0 = ksm[(n * 8 + g) * KSs + kk * 8 + t];
                    uint32_t b1 = ksm[(n * 8 + g) * KSs + kk * 8 + t + 4];
                    mma_tf32(s[n], qf[kk], b0, b1);
                }
            }

            // ---- causal mask (only the last two tiles can straddle) ----
            if (kvbase + BN - 1 > qbase) {
                const int q_lo = qbase + mrow + g;
                const int q_hi = q_lo + 8;
#pragma unroll
                for (int n = 0; n < 8; n++) {
                    int c = kvbase + n * 8 + t * 2;
                    if (c     > q_lo) s[n][0] = NEGINF;
                    if (c + 1 > q_lo) s[n][1] = NEGINF;
                    if (c     > q_hi) s[n][2] = NEGINF;
                    if (c + 1 > q_hi) s[n][3] = NEGINF;
                }
            }

            // ---- online softmax ----
            float tl = NEGINF, th = NEGINF;
#pragma unroll
            for (int n = 0; n < 8; n++) {
                tl = fmaxf(tl, fmaxf(s[n][0], s[n][1]));
                th = fmaxf(th, fmaxf(s[n][2], s[n][3]));
            }
            tl = fmaxf(tl, __shfl_xor_sync(0xffffffffu, tl, 1));
            tl = fmaxf(tl, __shfl_xor_sync(0xffffffffu, tl, 2));
            th = fmaxf(th, __shfl_xor_sync(0xffffffffu, th, 1));
            th = fmaxf(th, __shfl_xor_sync(0xffffffffu, th, 2));

            float mn_lo = fmaxf(m_lo, tl);
            float mn_hi = fmaxf(m_hi, th);
            float al = ex2f(m_lo - mn_lo);
            float ah = ex2f(m_hi - mn_hi);
            m_lo = mn_lo; m_hi = mn_hi;

            float sl = 0.f, sh = 0.f;
#pragma unroll
            for (int n = 0; n < 8; n++) {
                s[n][0] = ex2f(s[n][0] - m_lo);
                s[n][1] = ex2f(s[n][1] - m_lo);
                s[n][2] = ex2f(s[n][2] - m_hi);
                s[n][3] = ex2f(s[n][3] - m_hi);
                sl += s[n][0] + s[n][1];
                sh += s[n][2] + s[n][3];
            }
            l_lo = l_lo * al + sl;
            l_hi = l_hi * ah + sh;
#pragma unroll
            for (int nd = 0; nd < 8; nd++) {
                o[nd][0] *= al; o[nd][1] *= al;
                o[nd][2] *= ah; o[nd][3] *= ah;
            }

            // ---- O += P V : C-layout -> A-layout via shuffles, then mma ----
            const int  src1 = (lane & ~3) | (t >> 1);
            const int  src2 = src1 + 2;
            const bool oddc = (t & 1);
#pragma unroll
            for (int kk = 0; kk < 8; kk++) {
                uint32_t u0 = f2tf(s[kk][0]), u1 = f2tf(s[kk][1]);
                uint32_t u2 = f2tf(s[kk][2]), u3 = f2tf(s[kk][3]);
                uint32_t ap[4];
                uint32_t w0 = __shfl_sync(0xffffffffu, u0, src1);
                uint32_t w1 = __shfl_sync(0xffffffffu, u1, src1);
                ap[0] = oddc ? w1 : w0;
                uint32_t w2 = __shfl_sync(0xffffffffu, u2, src1);
                uint32_t w3 = __shfl_sync(0xffffffffu, u3, src1);
                ap[1] = oddc ? w3 : w2;
                uint32_t w4 = __shfl_sync(0xffffffffu, u0, src2);
                uint32_t w5 = __shfl_sync(0xffffffffu, u1, src2);
                ap[2] = oddc ? w5 : w4;
                uint32_t w6 = __shfl_sync(0xffffffffu, u2, src2);
                uint32_t w7 = __shfl_sync(0xffffffffu, u3, src2);
                ap[3] = oddc ? w7 : w6;
#pragma unroll
                for (int nd = 0; nd < 8; nd++) {
                    uint32_t b0 = vsm[(kk * 8 + t)     * VSs + nd * 8 + g];
                    uint32_t b1 = vsm[(kk * 8 + t + 4) * VSs + nd * 8 + g];
                    mma_tf32(o[nd], ap, b0, b1);
                }
            }
        }
    }

    // ---- finalize: row-sum reduce, normalize, store ----
    l_lo += __shfl_xor_sync(0xffffffffu, l_lo, 1);
    l_lo += __shfl_xor_sync(0xffffffffu, l_lo, 2);
    l_hi += __shfl_xor_sync(0xffffffffu, l_hi, 1);
    l_hi += __shfl_xor_sync(0xffffffffu, l_hi, 2);
    const float il = 1.f / l_lo;
    const float ih = 1.f / l_hi;

    const int r_lo = qbase + mrow + g;
#pragma unroll
    for (int nd = 0; nd < 8; nd++) {
        int col = nd * 8 + t * 2;
        float2 v0 = make_float2(o[nd][0] * il, o[nd][1] * il);
        float2 v1 = make_float2(o[nd][2] * ih, o[nd][3] * ih);
        *reinterpret_cast<float2*>(Op + (size_t)r_lo * Dd + col)       = v0;
        *reinterpret_cast<float2*>(Op + (size_t)(r_lo + 8) * Dd + col) = v1;
    }
}

}  // namespace

extern "C" void kernel_launch(void* const* d_in, const int* in_sizes, int n_in,
                              void* d_out, int out_size) {
    (void)in_sizes; (void)n_in; (void)out_size;
    const float* q = (const float*)d_in[0];
    const float* k = (const float*)d_in[1];
    const float* v = (const float*)d_in[2];
    float*       o = (float*)d_out;

    cudaFuncSetAttribute(fa_fwd, cudaFuncAttributeMaxDynamicSharedMemorySize,
                         SMEM_BYTES);
    dim3 grid(Tt / BM, Bb * Hh);
    fa_fwd<<<grid, 256, SMEM_BYTES>>>(q, k, v, o);
}

// round 4
// speedup vs baseline: 1.9447x; 1.9447x over previous
#include <cuda_runtime.h>
#include <cuda_fp16.h>
#include <cstdint>

namespace {

constexpr int Bb = 2, Hh = 16, Tt = 4096, Dd = 64;
constexpr int BM = 128;            // q rows per CTA
constexpr int BN = 64;             // kv rows per tile
constexpr int QSTR = 72;           // smem row strides (halves): 144B, 16B-aligned, conflict-free ldmatrix
constexpr int KSTR = 72;
constexpr int VSTR = 72;
constexpr int SMEM_HALVES = BM * QSTR + 2 * BN * KSTR + 2 * BN * VSTR;
constexpr int SMEM_BYTES = SMEM_HALVES * 2;
constexpr float QSCALE = 0.125f * 1.44269504088896340736f;  // 1/sqrt(64) * log2(e)

__device__ __forceinline__ uint32_t cvta_s(const void* p) {
    return (uint32_t)__cvta_generic_to_shared(p);
}

__device__ __forceinline__ float ex2f(float x) {
    float y;
    asm("ex2.approx.f32 %0, %1;" : "=f"(y) : "f"(x));
    return y;
}

__device__ __forceinline__ void ldsm4(uint32_t& r0, uint32_t& r1, uint32_t& r2,
                                      uint32_t& r3, uint32_t addr) {
    asm volatile("ldmatrix.sync.aligned.m8n8.x4.shared.b16 {%0,%1,%2,%3}, [%4];"
                 : "=r"(r0), "=r"(r1), "=r"(r2), "=r"(r3) : "r"(addr));
}

__device__ __forceinline__ void ldsm4t(uint32_t& r0, uint32_t& r1, uint32_t& r2,
                                       uint32_t& r3, uint32_t addr) {
    asm volatile("ldmatrix.sync.aligned.m8n8.x4.trans.shared.b16 {%0,%1,%2,%3}, [%4];"
                 : "=r"(r0), "=r"(r1), "=r"(r2), "=r"(r3) : "r"(addr));
}

__device__ __forceinline__ void mma16816(float d[4], const uint32_t a[4],
                                         uint32_t b0, uint32_t b1) {
    asm volatile(
        "mma.sync.aligned.m16n8k16.row.col.f32.f16.f16.f32 "
        "{%0,%1,%2,%3}, {%4,%5,%6,%7}, {%8,%9}, {%0,%1,%2,%3};"
        : "+f"(d[0]), "+f"(d[1]), "+f"(d[2]), "+f"(d[3])
        : "r"(a[0]), "r"(a[1]), "r"(a[2]), "r"(a[3]), "r"(b0), "r"(b1));
}

__device__ __forceinline__ uint32_t packh2(float a, float b) {
    uint32_t r;
    asm("cvt.rn.f16x2.f32 %0, %2, %1;" : "=r"(r) : "f"(a), "f"(b));
    return r;   // lower half = a, upper = b
}

__device__ __forceinline__ void stconv4(__half* dst, float4 a, float sc) {
    *reinterpret_cast<__half2*>(dst)     = __floats2half2_rn(a.x * sc, a.y * sc);
    *reinterpret_cast<__half2*>(dst + 2) = __floats2half2_rn(a.z * sc, a.w * sc);
}

__global__ void __launch_bounds__(256, 1)
fa_fwd(const float* __restrict__ Q, const float* __restrict__ K,
       const float* __restrict__ V, float* __restrict__ O) {
    extern __shared__ __half sm_[];
    __half* qs = sm_;                               // 128 x 72
    __half* kb = sm_ + BM * QSTR;                   // 2 x 64 x 72
    __half* vb = kb + 2 * BN * KSTR;                // 2 x 64 x 72

    const int tid  = threadIdx.x;
    const int warp = tid >> 5;
    const int lane = tid & 31;
    const int g = lane >> 2;
    const int t = lane & 3;

    const int bh    = blockIdx.y;
    const int qb    = (int)gridDim.x - 1 - (int)blockIdx.x;  // longest-first
    const int qbase = qb * BM;
    const size_t base = (size_t)bh * Tt * Dd;
    const float* Qp = Q + base;
    const float* Kp = K + base;
    const float* Vp = V + base;
    float*       Op = O + base;

    // ---- Q tile -> smem fp16 (pre-scaled) ----
    {
        int r  = tid >> 1;
        int c0 = (tid & 1) * 32;
        const float4* src = reinterpret_cast<const float4*>(
            Qp + (size_t)(qbase + r) * Dd + c0);
        __half* dst = qs + r * QSTR + c0;
#pragma unroll
        for (int i = 0; i < 8; i++) stconv4(dst + i * 4, src[i], QSCALE);
    }
    // ---- preload KV tile 0 into buffer 0 ----
    {
        int r  = tid >> 2;
        int c0 = (tid & 3) * 16;
        const float4* sk = reinterpret_cast<const float4*>(Kp + (size_t)r * Dd + c0);
        const float4* sv = reinterpret_cast<const float4*>(Vp + (size_t)r * Dd + c0);
        __half* dk = kb + r * KSTR + c0;
        __half* dv = vb + r * VSTR + c0;
#pragma unroll
        for (int i = 0; i < 4; i++) stconv4(dk + i * 4, sk[i], 1.f);
#pragma unroll
        for (int i = 0; i < 4; i++) stconv4(dv + i * 4, sv[i], 1.f);
    }
    __syncthreads();

    // ---- Q A-fragments (held in registers) ----
    const int mrow = warp * 16;
    uint32_t qa[4][4];
#pragma unroll
    for (int ks = 0; ks < 4; ks++) {
        int row = mrow + (lane & 7) + ((lane >> 3) & 1) * 8;
        int col = ks * 16 + (lane >> 4) * 8;
        ldsm4(qa[ks][0], qa[ks][1], qa[ks][2], qa[ks][3],
              cvta_s(qs + row * QSTR + col));
    }

    float o[8][4];
#pragma unroll
    for (int nd = 0; nd < 8; nd++) {
        o[nd][0] = 0.f; o[nd][1] = 0.f; o[nd][2] = 0.f; o[nd][3] = 0.f;
    }
    const float NEGINF = __int_as_float(0xff800000u);
    float m_lo = NEGINF, m_hi = NEGINF, l_lo = 0.f, l_hi = 0.f;

    const bool warp_any = true;
    (void)warp_any;

    const int jmax = 2 * qb + 1;
    for (int j = 0; j <= jmax; j++) {
        const int cur = j & 1;
        const int kvbase = j * BN;

        // ---- prefetch next tile into registers (latency overlapped with compute) ----
        float4 kr[4], vr[4];
        const bool pf = (j < jmax);
        int pr = tid >> 2, pc = (tid & 3) * 16;
        if (pf) {
            const float4* sk = reinterpret_cast<const float4*>(
                Kp + (size_t)(kvbase + BN + pr) * Dd + pc);
            const float4* sv = reinterpret_cast<const float4*>(
                Vp + (size_t)(kvbase + BN + pr) * Dd + pc);
#pragma unroll
            for (int i = 0; i < 4; i++) kr[i] = sk[i];
#pragma unroll
            for (int i = 0; i < 4; i++) vr[i] = sv[i];
        }

        const __half* kt = kb + cur * BN * KSTR;
        const __half* vt = vb + cur * BN * VSTR;

        const bool active = (kvbase <= qbase + mrow + 15);
        if (active) {
            // ---- S = Q K^T ----
            float s[8][4];
#pragma unroll
            for (int n = 0; n < 8; n++) {
                s[n][0] = 0.f; s[n][1] = 0.f; s[n][2] = 0.f; s[n][3] = 0.f;
            }
#pragma unroll
            for (int n = 0; n < 8; n++) {
                int rowa = 8 * n + (lane & 7);
                int cola = 8 * (lane >> 3);
                uint32_t b[8];
                ldsm4(b[0], b[1], b[2], b[3], cvta_s(kt + rowa * KSTR + cola));
                ldsm4(b[4], b[5], b[6], b[7], cvta_s(kt + rowa * KSTR + cola + 32));
#pragma unroll
                for (int ks = 0; ks < 4; ks++)
                    mma16816(s[n], qa[ks], b[2 * ks], b[2 * ks + 1]);
            }

            // ---- causal mask (straddling tiles only) ----
            if (kvbase + BN - 1 > qbase) {
                const int q_lo = qbase + mrow + g;
                const int q_hi = q_lo + 8;
#pragma unroll
                for (int n = 0; n < 8; n++) {
                    int c = kvbase + n * 8 + t * 2;
                    if (c     > q_lo) s[n][0] = NEGINF;
                    if (c + 1 > q_lo) s[n][1] = NEGINF;
                    if (c     > q_hi) s[n][2] = NEGINF;
                    if (c + 1 > q_hi) s[n][3] = NEGINF;
                }
            }

            // ---- online softmax (exp2 domain) ----
            float tl = NEGINF, th = NEGINF;
#pragma unroll
            for (int n = 0; n < 8; n++) {
                tl = fmaxf(tl, fmaxf(s[n][0], s[n][1]));
                th = fmaxf(th, fmaxf(s[n][2], s[n][3]));
            }
            tl = fmaxf(tl, __shfl_xor_sync(0xffffffffu, tl, 1));
            tl = fmaxf(tl, __shfl_xor_sync(0xffffffffu, tl, 2));
            th = fmaxf(th, __shfl_xor_sync(0xffffffffu, th, 1));
            th = fmaxf(th, __shfl_xor_sync(0xffffffffu, th, 2));

            float mn_lo = fmaxf(m_lo, tl);
            float mn_hi = fmaxf(m_hi, th);
            float al = ex2f(m_lo - mn_lo);
            float ah = ex2f(m_hi - mn_hi);
            m_lo = mn_lo; m_hi = mn_hi;

            float sl = 0.f, sh = 0.f;
            uint32_t ph[8][2];
#pragma unroll
            for (int n = 0; n < 8; n++) {
                s[n][0] = ex2f(s[n][0] - m_lo);
                s[n][1] = ex2f(s[n][1] - m_lo);
                s[n][2] = ex2f(s[n][2] - m_hi);
                s[n][3] = ex2f(s[n][3] - m_hi);
                sl += s[n][0] + s[n][1];
                sh += s[n][2] + s[n][3];
                ph[n][0] = packh2(s[n][0], s[n][1]);   // == PV A-fragment regs
                ph[n][1] = packh2(s[n][2], s[n][3]);
            }
            l_lo = l_lo * al + sl;
            l_hi = l_hi * ah + sh;
#pragma unroll
            for (int nd = 0; nd < 8; nd++) {
                o[nd][0] *= al; o[nd][1] *= al;
                o[nd][2] *= ah; o[nd][3] *= ah;
            }

            // ---- O += P V ----
#pragma unroll
            for (int ks = 0; ks < 4; ks++) {
                const uint32_t a[4] = {ph[2 * ks][0], ph[2 * ks][1],
                                       ph[2 * ks + 1][0], ph[2 * ks + 1][1]};
                int rowv = 16 * ks + 8 * ((lane >> 3) & 1) + (lane & 7);
#pragma unroll
                for (int p = 0; p < 4; p++) {
                    int colv = 8 * (2 * p + (lane >> 4));
                    uint32_t r0, r1, r2, r3;
                    ldsm4t(r0, r1, r2, r3, cvta_s(vt + rowv * VSTR + colv));
                    mma16816(o[2 * p],     a, r0, r1);
                    mma16816(o[2 * p + 1], a, r2, r3);
                }
            }
        }

        // ---- store prefetched tile into the other buffer ----
        if (pf) {
            __half* dk = kb + (cur ^ 1) * BN * KSTR + pr * KSTR + pc;
            __half* dv = vb + (cur ^ 1) * BN * VSTR + pr * VSTR + pc;
#pragma unroll
            for (int i = 0; i < 4; i++) stconv4(dk + i * 4, kr[i], 1.f);
#pragma unroll
            for (int i = 0; i < 4; i++) stconv4(dv + i * 4, vr[i], 1.f);
        }
        __syncthreads();
    }

    // ---- finalize ----
    l_lo += __shfl_xor_sync(0xffffffffu, l_lo, 1);
    l_lo += __shfl_xor_sync(0xffffffffu, l_lo, 2);
    l_hi += __shfl_xor_sync(0xffffffffu, l_hi, 1);
    l_hi += __shfl_xor_sync(0xffffffffu, l_hi, 2);
    const float il = 1.f / l_lo;
    const float ih = 1.f / l_hi;

    const int r_lo = qbase + mrow + g;
#pragma unroll
    for (int nd = 0; nd < 8; nd++) {
        int col = nd * 8 + t * 2;
        float2 v0 = make_float2(o[nd][0] * il, o[nd][1] * il);
        float2 v1 = make_float2(o[nd][2] * ih, o[nd][3] * ih);
        *reinterpret_cast<float2*>(Op + (size_t)r_lo * Dd + col)       = v0;
        *reinterpret_cast<float2*>(Op + (size_t)(r_lo + 8) * Dd + col) = v1;
    }
}

}  // namespace

extern "C" void kernel_launch(void* const* d_in, const int* in_sizes, int n_in,
                              void* d_out, int out_size) {
    (void)in_sizes; (void)n_in; (void)out_size;
    const float* q = (const float*)d_in[0];
    const float* k = (const float*)d_in[1];
    const float* v = (const float*)d_in[2];
    float*       o = (float*)d_out;

    cudaFuncSetAttribute(fa_fwd, cudaFuncAttributeMaxDynamicSharedMemorySize,
                         SMEM_BYTES);
    dim3 grid(Tt / BM, Bb * Hh);
    fa_fwd<<<grid, 256, SMEM_BYTES>>>(q, k, v, o);
}

// round 5
// speedup vs baseline: 1.9466x; 1.0010x over previous
#include <cuda_runtime.h>
#include <cuda_fp16.h>
#include <cstdint>

namespace {

constexpr int Bb = 2, Hh = 16, Tt = 4096, Dd = 64;
constexpr int BM = 128;            // q rows per CTA
constexpr int BN = 64;             // kv rows per tile
constexpr int QSTR = 72;           // smem row strides (halves): 144B, 16B-aligned, conflict-free ldmatrix
constexpr int KSTR = 72;
constexpr int VSTR = 72;
constexpr int SMEM_HALVES = BM * QSTR + 2 * BN * KSTR + 2 * BN * VSTR;
constexpr int SMEM_BYTES = SMEM_HALVES * 2;
constexpr float QSCALE = 0.125f * 1.44269504088896340736f;  // 1/sqrt(64) * log2(e)

__device__ __forceinline__ uint32_t cvta_s(const void* p) {
    return (uint32_t)__cvta_generic_to_shared(p);
}

__device__ __forceinline__ float ex2f(float x) {
    float y;
    asm("ex2.approx.f32 %0, %1;" : "=f"(y) : "f"(x));
    return y;
}

__device__ __forceinline__ void ldsm4(uint32_t& r0, uint32_t& r1, uint32_t& r2,
                                      uint32_t& r3, uint32_t addr) {
    asm volatile("ldmatrix.sync.aligned.m8n8.x4.shared.b16 {%0,%1,%2,%3}, [%4];"
                 : "=r"(r0), "=r"(r1), "=r"(r2), "=r"(r3) : "r"(addr));
}

__device__ __forceinline__ void ldsm4t(uint32_t& r0, uint32_t& r1, uint32_t& r2,
                                       uint32_t& r3, uint32_t addr) {
    asm volatile("ldmatrix.sync.aligned.m8n8.x4.trans.shared.b16 {%0,%1,%2,%3}, [%4];"
                 : "=r"(r0), "=r"(r1), "=r"(r2), "=r"(r3) : "r"(addr));
}

__device__ __forceinline__ void mma16816(float d[4], const uint32_t a[4],
                                         uint32_t b0, uint32_t b1) {
    asm volatile(
        "mma.sync.aligned.m16n8k16.row.col.f32.f16.f16.f32 "
        "{%0,%1,%2,%3}, {%4,%5,%6,%7}, {%8,%9}, {%0,%1,%2,%3};"
        : "+f"(d[0]), "+f"(d[1]), "+f"(d[2]), "+f"(d[3])
        : "r"(a[0]), "r"(a[1]), "r"(a[2]), "r"(a[3]), "r"(b0), "r"(b1));
}

__device__ __forceinline__ uint32_t packh2(float a, float b) {
    uint32_t r;
    asm("cvt.rn.f16x2.f32 %0, %2, %1;" : "=r"(r) : "f"(a), "f"(b));
    return r;   // lower half = a, upper = b
}

__device__ __forceinline__ void stconv4(__half* dst, float4 a, float sc) {
    *reinterpret_cast<__half2*>(dst)     = __floats2half2_rn(a.x * sc, a.y * sc);
    *reinterpret_cast<__half2*>(dst + 2) = __floats2half2_rn(a.z * sc, a.w * sc);
}

__global__ void __launch_bounds__(256, 1)
fa_fwd(const float* __restrict__ Q, const float* __restrict__ K,
       const float* __restrict__ V, float* __restrict__ O) {
    extern __shared__ __half sm_[];
    __half* qs = sm_;                               // 128 x 72
    __half* kb = sm_ + BM * QSTR;                   // 2 x 64 x 72
    __half* vb = kb + 2 * BN * KSTR;                // 2 x 64 x 72

    const int tid  = threadIdx.x;
    const int warp = tid >> 5;
    const int lane = tid & 31;
    const int g = lane >> 2;
    const int t = lane & 3;

    const int bh    = blockIdx.y;
    const int qb    = (int)gridDim.x - 1 - (int)blockIdx.x;  // longest-first
    const int qbase = qb * BM;
    const size_t base = (size_t)bh * Tt * Dd;
    const float* Qp = Q + base;
    const float* Kp = K + base;
    const float* Vp = V + base;
    float*       Op = O + base;

    // ---- Q tile -> smem fp16 (pre-scaled) ----
    {
        int r  = tid >> 1;
        int c0 = (tid & 1) * 32;
        const float4* src = reinterpret_cast<const float4*>(
            Qp + (size_t)(qbase + r) * Dd + c0);
        __half* dst = qs + r * QSTR + c0;
#pragma unroll
        for (int i = 0; i < 8; i++) stconv4(dst + i * 4, src[i], QSCALE);
    }
    // ---- preload KV tile 0 into buffer 0 ----
    {
        int r  = tid >> 2;
        int c0 = (tid & 3) * 16;
        const float4* sk = reinterpret_cast<const float4*>(Kp + (size_t)r * Dd + c0);
        const float4* sv = reinterpret_cast<const float4*>(Vp + (size_t)r * Dd + c0);
        __half* dk = kb + r * KSTR + c0;
        __half* dv = vb + r * VSTR + c0;
#pragma unroll
        for (int i = 0; i < 4; i++) stconv4(dk + i * 4, sk[i], 1.f);
#pragma unroll
        for (int i = 0; i < 4; i++) stconv4(dv + i * 4, sv[i], 1.f);
    }
    __syncthreads();

    // ---- Q A-fragments (held in registers) ----
    const int mrow = warp * 16;
    uint32_t qa[4][4];
#pragma unroll
    for (int ks = 0; ks < 4; ks++) {
        int row = mrow + (lane & 7) + ((lane >> 3) & 1) * 8;
        int col = ks * 16 + (lane >> 4) * 8;
        ldsm4(qa[ks][0], qa[ks][1], qa[ks][2], qa[ks][3],
              cvta_s(qs + row * QSTR + col));
    }

    float o[8][4];
#pragma unroll
    for (int nd = 0; nd < 8; nd++) {
        o[nd][0] = 0.f; o[nd][1] = 0.f; o[nd][2] = 0.f; o[nd][3] = 0.f;
    }
    const float NEGINF = __int_as_float(0xff800000u);
    float m_lo = NEGINF, m_hi = NEGINF, l_lo = 0.f, l_hi = 0.f;

    const bool warp_any = true;
    (void)warp_any;

    const int jmax = 2 * qb + 1;
    for (int j = 0; j <= jmax; j++) {
        const int cur = j & 1;
        const int kvbase = j * BN;

        // ---- prefetch next tile into registers (latency overlapped with compute) ----
        float4 kr[4], vr[4];
        const bool pf = (j < jmax);
        int pr = tid >> 2, pc = (tid & 3) * 16;
        if (pf) {
            const float4* sk = reinterpret_cast<const float4*>(
                Kp + (size_t)(kvbase + BN + pr) * Dd + pc);
            const float4* sv = reinterpret_cast<const float4*>(
                Vp + (size_t)(kvbase + BN + pr) * Dd + pc);
#pragma unroll
            for (int i = 0; i < 4; i++) kr[i] = sk[i];
#pragma unroll
            for (int i = 0; i < 4; i++) vr[i] = sv[i];
        }

        const __half* kt = kb + cur * BN * KSTR;
        const __half* vt = vb + cur * BN * VSTR;

        const bool active = (kvbase <= qbase + mrow + 15);
        if (active) {
            // ---- S = Q K^T ----
            float s[8][4];
#pragma unroll
            for (int n = 0; n < 8; n++) {
                s[n][0] = 0.f; s[n][1] = 0.f; s[n][2] = 0.f; s[n][3] = 0.f;
            }
#pragma unroll
            for (int n = 0; n < 8; n++) {
                int rowa = 8 * n + (lane & 7);
                int cola = 8 * (lane >> 3);
                uint32_t b[8];
                ldsm4(b[0], b[1], b[2], b[3], cvta_s(kt + rowa * KSTR + cola));
                ldsm4(b[4], b[5], b[6], b[7], cvta_s(kt + rowa * KSTR + cola + 32));
#pragma unroll
                for (int ks = 0; ks < 4; ks++)
                    mma16816(s[n], qa[ks], b[2 * ks], b[2 * ks + 1]);
            }

            // ---- causal mask (straddling tiles only) ----
            if (kvbase + BN - 1 > qbase) {
                const int q_lo = qbase + mrow + g;
                const int q_hi = q_lo + 8;
#pragma unroll
                for (int n = 0; n < 8; n++) {
                    int c = kvbase + n * 8 + t * 2;
                    if (c     > q_lo) s[n][0] = NEGINF;
                    if (c + 1 > q_lo) s[n][1] = NEGINF;
                    if (c     > q_hi) s[n][2] = NEGINF;
                    if (c + 1 > q_hi) s[n][3] = NEGINF;
                }
            }

            // ---- online softmax (exp2 domain) ----
            float tl = NEGINF, th = NEGINF;
#pragma unroll
            for (int n = 0; n < 8; n++) {
                tl = fmaxf(tl, fmaxf(s[n][0], s[n][1]));
                th = fmaxf(th, fmaxf(s[n][2], s[n][3]));
            }
            tl = fmaxf(tl, __shfl_xor_sync(0xffffffffu, tl, 1));
            tl = fmaxf(tl, __shfl_xor_sync(0xffffffffu, tl, 2));
            th = fmaxf(th, __shfl_xor_sync(0xffffffffu, th, 1));
            th = fmaxf(th, __shfl_xor_sync(0xffffffffu, th, 2));

            float mn_lo = fmaxf(m_lo, tl);
            float mn_hi = fmaxf(m_hi, th);
            float al = ex2f(m_lo - mn_lo);
            float ah = ex2f(m_hi - mn_hi);
            m_lo = mn_lo; m_hi = mn_hi;

            float sl = 0.f, sh = 0.f;
            uint32_t ph[8][2];
#pragma unroll
            for (int n = 0; n < 8; n++) {
                s[n][0] = ex2f(s[n][0] - m_lo);
                s[n][1] = ex2f(s[n][1] - m_lo);
                s[n][2] = ex2f(s[n][2] - m_hi);
                s[n][3] = ex2f(s[n][3] - m_hi);
                sl += s[n][0] + s[n][1];
                sh += s[n][2] + s[n][3];
                ph[n][0] = packh2(s[n][0], s[n][1]);   // == PV A-fragment regs
                ph[n][1] = packh2(s[n][2], s[n][3]);
            }
            l_lo = l_lo * al + sl;
            l_hi = l_hi * ah + sh;
#pragma unroll
            for (int nd = 0; nd < 8; nd++) {
                o[nd][0] *= al; o[nd][1] *= al;
                o[nd][2] *= ah; o[nd][3] *= ah;
            }

            // ---- O += P V ----
#pragma unroll
            for (int ks = 0; ks < 4; ks++) {
                const uint32_t a[4] = {ph[2 * ks][0], ph[2 * ks][1],
                                       ph[2 * ks + 1][0], ph[2 * ks + 1][1]};
                int rowv = 16 * ks + 8 * ((lane >> 3) & 1) + (lane & 7);
#pragma unroll
                for (int p = 0; p < 4; p++) {
                    int colv = 8 * (2 * p + (lane >> 4));
                    uint32_t r0, r1, r2, r3;
                    ldsm4t(r0, r1, r2, r3, cvta_s(vt + rowv * VSTR + colv));
                    mma16816(o[2 * p],     a, r0, r1);
                    mma16816(o[2 * p + 1], a, r2, r3);
                }
            }
        }

        // ---- store prefetched tile into the other buffer ----
        if (pf) {
            __half* dk = kb + (cur ^ 1) * BN * KSTR + pr * KSTR + pc;
            __half* dv = vb + (cur ^ 1) * BN * VSTR + pr * VSTR + pc;
#pragma unroll
            for (int i = 0; i < 4; i++) stconv4(dk + i * 4, kr[i], 1.f);
#pragma unroll
            for (int i = 0; i < 4; i++) stconv4(dv + i * 4, vr[i], 1.f);
        }
        __syncthreads();
    }

    // ---- finalize ----
    l_lo += __shfl_xor_sync(0xffffffffu, l_lo, 1);
    l_lo += __shfl_xor_sync(0xffffffffu, l_lo, 2);
    l_hi += __shfl_xor_sync(0xffffffffu, l_hi, 1);
    l_hi += __shfl_xor_sync(0xffffffffu, l_hi, 2);
    const float il = 1.f / l_lo;
    const float ih = 1.f / l_hi;

    const int r_lo = qbase + mrow + g;
#pragma unroll
    for (int nd = 0; nd < 8; nd++) {
        int col = nd * 8 + t * 2;
        float2 v0 = make_float2(o[nd][0] * il, o[nd][1] * il);
        float2 v1 = make_float2(o[nd][2] * ih, o[nd][3] * ih);
        *reinterpret_cast<float2*>(Op + (size_t)r_lo * Dd + col)       = v0;
        *reinterpret_cast<float2*>(Op + (size_t)(r_lo + 8) * Dd + col) = v1;
    }
}

}  // namespace

extern "C" void kernel_launch(void* const* d_in, const int* in_sizes, int n_in,
                              void* d_out, int out_size) {
    (void)in_sizes; (void)n_in; (void)out_size;
    const float* q = (const float*)d_in[0];
    const float* k = (const float*)d_in[1];
    const float* v = (const float*)d_in[2];
    float*       o = (float*)d_out;

    cudaFuncSetAttribute(fa_fwd, cudaFuncAttributeMaxDynamicSharedMemorySize,
                         SMEM_BYTES);
    dim3 grid(Tt / BM, Bb * Hh);
    fa_fwd<<<grid, 256, SMEM_BYTES>>>(q, k, v, o);
}

// round 6
// speedup vs baseline: 1.9474x; 1.0004x over previous
#include <cuda_runtime.h>
#include <cuda_fp16.h>
#include <cstdint>

namespace {

constexpr int Bb = 2, Hh = 16, Tt = 4096, Dd = 64;
constexpr int BM = 128;            // q rows per CTA
constexpr int BN = 64;             // kv rows per tile
constexpr int QSTR = 72;           // smem row strides (halves): 144B, 16B-aligned, conflict-free ldmatrix
constexpr int KSTR = 72;
constexpr int VSTR = 72;
constexpr int SMEM_HALVES = BM * QSTR + 2 * BN * KSTR + 2 * BN * VSTR;
constexpr int SMEM_BYTES = SMEM_HALVES * 2;
constexpr float QSCALE = 0.125f * 1.44269504088896340736f;  // 1/sqrt(64) * log2(e)

__device__ __forceinline__ uint32_t cvta_s(const void* p) {
    return (uint32_t)__cvta_generic_to_shared(p);
}

__device__ __forceinline__ float ex2f(float x) {
    float y;
    asm("ex2.approx.f32 %0, %1;" : "=f"(y) : "f"(x));
    return y;
}

__device__ __forceinline__ void ldsm4(uint32_t& r0, uint32_t& r1, uint32_t& r2,
                                      uint32_t& r3, uint32_t addr) {
    asm volatile("ldmatrix.sync.aligned.m8n8.x4.shared.b16 {%0,%1,%2,%3}, [%4];"
                 : "=r"(r0), "=r"(r1), "=r"(r2), "=r"(r3) : "r"(addr));
}

__device__ __forceinline__ void ldsm4t(uint32_t& r0, uint32_t& r1, uint32_t& r2,
                                       uint32_t& r3, uint32_t addr) {
    asm volatile("ldmatrix.sync.aligned.m8n8.x4.trans.shared.b16 {%0,%1,%2,%3}, [%4];"
                 : "=r"(r0), "=r"(r1), "=r"(r2), "=r"(r3) : "r"(addr));
}

__device__ __forceinline__ void mma16816(float d[4], const uint32_t a[4],
                                         uint32_t b0, uint32_t b1) {
    asm volatile(
        "mma.sync.aligned.m16n8k16.row.col.f32.f16.f16.f32 "
        "{%0,%1,%2,%3}, {%4,%5,%6,%7}, {%8,%9}, {%0,%1,%2,%3};"
        : "+f"(d[0]), "+f"(d[1]), "+f"(d[2]), "+f"(d[3])
        : "r"(a[0]), "r"(a[1]), "r"(a[2]), "r"(a[3]), "r"(b0), "r"(b1));
}

__device__ __forceinline__ uint32_t packh2(float a, float b) {
    uint32_t r;
    asm("cvt.rn.f16x2.f32 %0, %2, %1;" : "=r"(r) : "f"(a), "f"(b));
    return r;   // lower half = a, upper = b
}

__device__ __forceinline__ void stconv4(__half* dst, float4 a, float sc) {
    *reinterpret_cast<__half2*>(dst)     = __floats2half2_rn(a.x * sc, a.y * sc);
    *reinterpret_cast<__half2*>(dst + 2) = __floats2half2_rn(a.z * sc, a.w * sc);
}

__global__ void __launch_bounds__(256, 1)
fa_fwd(const float* __restrict__ Q, const float* __restrict__ K,
       const float* __restrict__ V, float* __restrict__ O) {
    extern __shared__ __half sm_[];
    __half* qs = sm_;                               // 128 x 72
    __half* kb = sm_ + BM * QSTR;                   // 2 x 64 x 72
    __half* vb = kb + 2 * BN * KSTR;                // 2 x 64 x 72

    const int tid  = threadIdx.x;
    const int warp = tid >> 5;
    const int lane = tid & 31;
    const int g = lane >> 2;
    const int t = lane & 3;

    const int bh    = blockIdx.y;
    const int qb    = (int)gridDim.x - 1 - (int)blockIdx.x;  // longest-first
    const int qbase = qb * BM;
    const size_t base = (size_t)bh * Tt * Dd;
    const float* Qp = Q + base;
    const float* Kp = K + base;
    const float* Vp = V + base;
    float*       Op = O + base;

    // ---- Q tile -> smem fp16 (pre-scaled) ----
    {
        int r  = tid >> 1;
        int c0 = (tid & 1) * 32;
        const float4* src = reinterpret_cast<const float4*>(
            Qp + (size_t)(qbase + r) * Dd + c0);
        __half* dst = qs + r * QSTR + c0;
#pragma unroll
        for (int i = 0; i < 8; i++) stconv4(dst + i * 4, src[i], QSCALE);
    }
    // ---- preload KV tile 0 into buffer 0 ----
    {
        int r  = tid >> 2;
        int c0 = (tid & 3) * 16;
        const float4* sk = reinterpret_cast<const float4*>(Kp + (size_t)r * Dd + c0);
        const float4* sv = reinterpret_cast<const float4*>(Vp + (size_t)r * Dd + c0);
        __half* dk = kb + r * KSTR + c0;
        __half* dv = vb + r * VSTR + c0;
#pragma unroll
        for (int i = 0; i < 4; i++) stconv4(dk + i * 4, sk[i], 1.f);
#pragma unroll
        for (int i = 0; i < 4; i++) stconv4(dv + i * 4, sv[i], 1.f);
    }
    __syncthreads();

    // ---- Q A-fragments (held in registers) ----
    const int mrow = warp * 16;
    uint32_t qa[4][4];
#pragma unroll
    for (int ks = 0; ks < 4; ks++) {
        int row = mrow + (lane & 7) + ((lane >> 3) & 1) * 8;
        int col = ks * 16 + (lane >> 4) * 8;
        ldsm4(qa[ks][0], qa[ks][1], qa[ks][2], qa[ks][3],
              cvta_s(qs + row * QSTR + col));
    }

    float o[8][4];
#pragma unroll
    for (int nd = 0; nd < 8; nd++) {
        o[nd][0] = 0.f; o[nd][1] = 0.f; o[nd][2] = 0.f; o[nd][3] = 0.f;
    }
    const float NEGINF = __int_as_float(0xff800000u);
    float m_lo = NEGINF, m_hi = NEGINF, l_lo = 0.f, l_hi = 0.f;

    const bool warp_any = true;
    (void)warp_any;

    const int jmax = 2 * qb + 1;
    for (int j = 0; j <= jmax; j++) {
        const int cur = j & 1;
        const int kvbase = j * BN;

        // ---- prefetch next tile into registers (latency overlapped with compute) ----
        float4 kr[4], vr[4];
        const bool pf = (j < jmax);
        int pr = tid >> 2, pc = (tid & 3) * 16;
        if (pf) {
            const float4* sk = reinterpret_cast<const float4*>(
                Kp + (size_t)(kvbase + BN + pr) * Dd + pc);
            const float4* sv = reinterpret_cast<const float4*>(
                Vp + (size_t)(kvbase + BN + pr) * Dd + pc);
#pragma unroll
            for (int i = 0; i < 4; i++) kr[i] = sk[i];
#pragma unroll
            for (int i = 0; i < 4; i++) vr[i] = sv[i];
        }

        const __half* kt = kb + cur * BN * KSTR;
        const __half* vt = vb + cur * BN * VSTR;

        const bool active = (kvbase <= qbase + mrow + 15);
        if (active) {
            // ---- S = Q K^T ----
            float s[8][4];
#pragma unroll
            for (int n = 0; n < 8; n++) {
                s[n][0] = 0.f; s[n][1] = 0.f; s[n][2] = 0.f; s[n][3] = 0.f;
            }
#pragma unroll
            for (int n = 0; n < 8; n++) {
                int rowa = 8 * n + (lane & 7);
                int cola = 8 * (lane >> 3);
                uint32_t b[8];
                ldsm4(b[0], b[1], b[2], b[3], cvta_s(kt + rowa * KSTR + cola));
                ldsm4(b[4], b[5], b[6], b[7], cvta_s(kt + rowa * KSTR + cola + 32));
#pragma unroll
                for (int ks = 0; ks < 4; ks++)
                    mma16816(s[n], qa[ks], b[2 * ks], b[2 * ks + 1]);
            }

            // ---- causal mask (straddling tiles only) ----
            if (kvbase + BN - 1 > qbase) {
                const int q_lo = qbase + mrow + g;
                const int q_hi = q_lo + 8;
#pragma unroll
                for (int n = 0; n < 8; n++) {
                    int c = kvbase + n * 8 + t * 2;
                    if (c     > q_lo) s[n][0] = NEGINF;
                    if (c + 1 > q_lo) s[n][1] = NEGINF;
                    if (c     > q_hi) s[n][2] = NEGINF;
                    if (c + 1 > q_hi) s[n][3] = NEGINF;
                }
            }

            // ---- online softmax (exp2 domain) ----
            float tl = NEGINF, th = NEGINF;
#pragma unroll
            for (int n = 0; n < 8; n++) {
                tl = fmaxf(tl, fmaxf(s[n][0], s[n][1]));
                th = fmaxf(th, fmaxf(s[n][2], s[n][3]));
            }
            tl = fmaxf(tl, __shfl_xor_sync(0xffffffffu, tl, 1));
            tl = fmaxf(tl, __shfl_xor_sync(0xffffffffu, tl, 2));
            th = fmaxf(th, __shfl_xor_sync(0xffffffffu, th, 1));
            th = fmaxf(th, __shfl_xor_sync(0xffffffffu, th, 2));

            float mn_lo = fmaxf(m_lo, tl);
            float mn_hi = fmaxf(m_hi, th);
            float al = ex2f(m_lo - mn_lo);
            float ah = ex2f(m_hi - mn_hi);
            m_lo = mn_lo; m_hi = mn_hi;

            float sl = 0.f, sh = 0.f;
            uint32_t ph[8][2];
#pragma unroll
            for (int n = 0; n < 8; n++) {
                s[n][0] = ex2f(s[n][0] - m_lo);
                s[n][1] = ex2f(s[n][1] - m_lo);
                s[n][2] = ex2f(s[n][2] - m_hi);
                s[n][3] = ex2f(s[n][3] - m_hi);
                sl += s[n][0] + s[n][1];
                sh += s[n][2] + s[n][3];
                ph[n][0] = packh2(s[n][0], s[n][1]);   // == PV A-fragment regs
                ph[n][1] = packh2(s[n][2], s[n][3]);
            }
            l_lo = l_lo * al + sl;
            l_hi = l_hi * ah + sh;
#pragma unroll
            for (int nd = 0; nd < 8; nd++) {
                o[nd][0] *= al; o[nd][1] *= al;
                o[nd][2] *= ah; o[nd][3] *= ah;
            }

            // ---- O += P V ----
#pragma unroll
            for (int ks = 0; ks < 4; ks++) {
                const uint32_t a[4] = {ph[2 * ks][0], ph[2 * ks][1],
                                       ph[2 * ks + 1][0], ph[2 * ks + 1][1]};
                int rowv = 16 * ks + 8 * ((lane >> 3) & 1) + (lane & 7);
#pragma unroll
                for (int p = 0; p < 4; p++) {
                    int colv = 8 * (2 * p + (lane >> 4));
                    uint32_t r0, r1, r2, r3;
                    ldsm4t(r0, r1, r2, r3, cvta_s(vt + rowv * VSTR + colv));
                    mma16816(o[2 * p],     a, r0, r1);
                    mma16816(o[2 * p + 1], a, r2, r3);
                }
            }
        }

        // ---- store prefetched tile into the other buffer ----
        if (pf) {
            __half* dk = kb + (cur ^ 1) * BN * KSTR + pr * KSTR + pc;
            __half* dv = vb + (cur ^ 1) * BN * VSTR + pr * VSTR + pc;
#pragma unroll
            for (int i = 0; i < 4; i++) stconv4(dk + i * 4, kr[i], 1.f);
#pragma unroll
            for (int i = 0; i < 4; i++) stconv4(dv + i * 4, vr[i], 1.f);
        }
        __syncthreads();
    }

    // ---- finalize ----
    l_lo += __shfl_xor_sync(0xffffffffu, l_lo, 1);
    l_lo += __shfl_xor_sync(0xffffffffu, l_lo, 2);
    l_hi += __shfl_xor_sync(0xffffffffu, l_hi, 1);
    l_hi += __shfl_xor_sync(0xffffffffu, l_hi, 2);
    const float il = 1.f / l_lo;
    const float ih = 1.f / l_hi;

    const int r_lo = qbase + mrow + g;
#pragma unroll
    for (int nd = 0; nd < 8; nd++) {
        int col = nd * 8 + t * 2;
        float2 v0 = make_float2(o[nd][0] * il, o[nd][1] * il);
        float2 v1 = make_float2(o[nd][2] * ih, o[nd][3] * ih);
        *reinterpret_cast<float2*>(Op + (size_t)r_lo * Dd + col)       = v0;
        *reinterpret_cast<float2*>(Op + (size_t)(r_lo + 8) * Dd + col) = v1;
    }
}

}  // namespace

extern "C" void kernel_launch(void* const* d_in, const int* in_sizes, int n_in,
                              void* d_out, int out_size) {
    (void)in_sizes; (void)n_in; (void)out_size;
    const float* q = (const float*)d_in[0];
    const float* k = (const float*)d_in[1];
    const float* v = (const float*)d_in[2];
    float*       o = (float*)d_out;

    cudaFuncSetAttribute(fa_fwd, cudaFuncAttributeMaxDynamicSharedMemorySize,
                         SMEM_BYTES);
    dim3 grid(Tt / BM, Bb * Hh);
    fa_fwd<<<grid, 256, SMEM_BYTES>>>(q, k, v, o);
}